// round 3
// baseline (speedup 1.0000x reference)
#include <cuda_runtime.h>
#include <math.h>

#define THREADS 256
#define ROWS_PER_CTA 8   // one warp per row
#define MAXN 8192

// GLIF single timestep, fused matvec + elementwise.
// Warp-per-row, 8 rows per CTA; g staged in shared once per CTA.
// out[0:N) = v_new, out[N:2N) = spiked_soft.
__global__ __launch_bounds__(THREADS)
void glif_kernel(const float* __restrict__ x_in,
                 const float* __restrict__ w,
                 const float* __restrict__ v0,
                 const float* __restrict__ g,
                 const float* __restrict__ v_rest,
                 const float* __restrict__ tau_m,
                 const float* __restrict__ theta_s,
                 const float* __restrict__ theta_v,
                 float* __restrict__ out,
                 int n)
{
    __shared__ float4 gsh[MAXN / 4];   // 32 KB

    const int tid  = threadIdx.x;
    const int warp = tid >> 5;
    const int lane = tid & 31;
    const int nvec = n >> 2;           // float4 per row (8192 -> 2048)

    // Stage g into shared (cooperative, coalesced)
    const float4* __restrict__ g4 = reinterpret_cast<const float4*>(g);
    for (int j = tid; j < nvec; j += THREADS)
        gsh[j] = g4[j];
    __syncthreads();

    const int row = blockIdx.x * ROWS_PER_CTA + warp;
    const float4* __restrict__ wrow =
        reinterpret_cast<const float4*>(w + (size_t)row * (size_t)n);

    float acc0 = 0.f, acc1 = 0.f, acc2 = 0.f, acc3 = 0.f;

    // Each warp covers nvec float4 with 32 lanes: nvec/32 per lane,
    // processed in blocks of 8 front-batched LDG.128 for MLP.
    const int nblk = nvec >> 8;        // (nvec/32)/8 = 8 for n=8192
    for (int b = 0; b < nblk; b++) {
        const int base = (b << 8) + lane;   // block of 256 float4, lane-strided
        float4 wv[8];
        #pragma unroll
        for (int u = 0; u < 8; u++)
            wv[u] = wrow[base + (u << 5)];

        #pragma unroll
        for (int u = 0; u < 8; u++) {
            float4 gv = gsh[base + (u << 5)];
            acc0 = fmaf(wv[u].x, gv.x, acc0);
            acc1 = fmaf(wv[u].y, gv.y, acc1);
            acc2 = fmaf(wv[u].z, gv.z, acc2);
            acc3 = fmaf(wv[u].w, gv.w, acc3);
        }
    }

    float acc = (acc0 + acc1) + (acc2 + acc3);

    // Warp-level reduction (no cross-warp sync needed)
    #pragma unroll
    for (int off = 16; off > 0; off >>= 1)
        acc += __shfl_xor_sync(0xFFFFFFFFu, acc, off);

    if (lane == 0) {
        // GLIF elementwise epilogue for this neuron
        const float xi  = x_in[row];
        const float vr  = v_rest[row];
        const float tm  = tau_m[row];
        const float ths = theta_s[row];
        const float thv = theta_v[row];
        const float vin = v0[row];

        // I = sigmoid(w@g + x_in)
        const float z = acc + xi;
        const float I = 1.0f / (1.0f + expf(-z));

        // membrane integration
        const float v = vin + (vr - vin + I) / tm;

        const float thresh = ths + thv;
        // surrogate spike (accurate exp: value can be ~1e-20, rel-err matters)
        const float spiked_soft = 1.0f / (1.0f + expf(-(v - thresh)));
        // hard spike + reset-or-keep
        const float v_new = (v >= thresh) ? vr : v;

        out[row]     = v_new;
        out[n + row] = spiked_soft;
    }
}

extern "C" void kernel_launch(void* const* d_in, const int* in_sizes, int n_in,
                              void* d_out, int out_size)
{
    // metadata order: x_in, w, v, g, v_rest, tau_m, tau_g, theta_s, theta_v, b_s, a_v, b_v
    const float* x_in    = (const float*)d_in[0];
    const float* w       = (const float*)d_in[1];
    const float* v       = (const float*)d_in[2];
    const float* g       = (const float*)d_in[3];
    const float* v_rest  = (const float*)d_in[4];
    const float* tau_m   = (const float*)d_in[5];
    // d_in[6] = tau_g (unused by returned outputs)
    const float* theta_s = (const float*)d_in[7];
    const float* theta_v = (const float*)d_in[8];
    // d_in[9..11] = b_s, a_v, b_v (only affect discarded hidden state)

    float* out = (float*)d_out;
    const int n = in_sizes[0];  // 8192

    glif_kernel<<<n / ROWS_PER_CTA, THREADS>>>(x_in, w, v, g, v_rest, tau_m,
                                               theta_s, theta_v, out, n);
}

// round 5
// speedup vs baseline: 1.1180x; 1.1180x over previous
#include <cuda_runtime.h>
#include <math.h>

#define THREADS 256
#define WARPS (THREADS / 32)
#define UNROLL 8   // 2048 float4 per row / 256 threads

// GLIF single timestep, fused matvec + elementwise.
// One CTA per neuron (row of w). Front-batched 8x LDG.128 per thread for MLP.
// out[0:N) = v_new, out[N:2N) = spiked_soft.
__global__ __launch_bounds__(THREADS)
void glif_kernel(const float* __restrict__ x_in,
                 const float* __restrict__ w,
                 const float* __restrict__ v0,
                 const float* __restrict__ g,
                 const float* __restrict__ v_rest,
                 const float* __restrict__ tau_m,
                 const float* __restrict__ theta_s,
                 const float* __restrict__ theta_v,
                 float* __restrict__ out,
                 int n)
{
    const int row = blockIdx.x;
    const int tid = threadIdx.x;

    const float4* __restrict__ wrow =
        reinterpret_cast<const float4*>(w + (size_t)row * (size_t)n);
    const float4* __restrict__ g4 = reinterpret_cast<const float4*>(g);

    // Front-batch: issue all 8 w-row loads before any consumption.
    // n = 8192 -> nvec = 2048 = THREADS * UNROLL exactly.
    float4 wv[UNROLL];
    #pragma unroll
    for (int u = 0; u < UNROLL; u++)
        wv[u] = wrow[tid + u * THREADS];

    float acc0 = 0.f, acc1 = 0.f, acc2 = 0.f, acc3 = 0.f;
    #pragma unroll
    for (int u = 0; u < UNROLL; u++) {
        float4 gv = g4[tid + u * THREADS];   // L1/L2-resident (32 KB, shared by all CTAs)
        acc0 = fmaf(wv[u].x, gv.x, acc0);
        acc1 = fmaf(wv[u].y, gv.y, acc1);
        acc2 = fmaf(wv[u].z, gv.z, acc2);
        acc3 = fmaf(wv[u].w, gv.w, acc3);
    }
    float acc = (acc0 + acc1) + (acc2 + acc3);

    // Warp reduction
    #pragma unroll
    for (int off = 16; off > 0; off >>= 1)
        acc += __shfl_xor_sync(0xFFFFFFFFu, acc, off);

    __shared__ float warp_sums[WARPS];
    if ((tid & 31) == 0) warp_sums[tid >> 5] = acc;
    __syncthreads();

    if (tid == 0) {
        float s = 0.0f;
        #pragma unroll
        for (int wgi = 0; wgi < WARPS; wgi++) s += warp_sums[wgi];

        // GLIF elementwise epilogue for this neuron
        const float xi  = x_in[row];
        const float vr  = v_rest[row];
        const float tm  = tau_m[row];
        const float ths = theta_s[row];
        const float thv = theta_v[row];
        const float vin = v0[row];

        // I = sigmoid(w@g + x_in)
        const float z = s + xi;
        const float I = 1.0f / (1.0f + expf(-z));

        // membrane integration
        const float v = vin + (vr - vin + I) / tm;

        const float thresh = ths + thv;
        // surrogate spike (accurate exp: value can be ~1e-20, rel-err matters)
        const float spiked_soft = 1.0f / (1.0f + expf(-(v - thresh)));
        // hard spike + reset-or-keep
        const float v_new = (v >= thresh) ? vr : v;

        out[row]     = v_new;
        out[n + row] = spiked_soft;
    }
}

extern "C" void kernel_launch(void* const* d_in, const int* in_sizes, int n_in,
                              void* d_out, int out_size)
{
    // metadata order: x_in, w, v, g, v_rest, tau_m, tau_g, theta_s, theta_v, b_s, a_v, b_v
    const float* x_in    = (const float*)d_in[0];
    const float* w       = (const float*)d_in[1];
    const float* v       = (const float*)d_in[2];
    const float* g       = (const float*)d_in[3];
    const float* v_rest  = (const float*)d_in[4];
    const float* tau_m   = (const float*)d_in[5];
    // d_in[6] = tau_g (unused by returned outputs)
    const float* theta_s = (const float*)d_in[7];
    const float* theta_v = (const float*)d_in[8];
    // d_in[9..11] = b_s, a_v, b_v (only affect discarded hidden state)

    float* out = (float*)d_out;
    const int n = in_sizes[0];  // 8192

    glif_kernel<<<n, THREADS>>>(x_in, w, v, g, v_rest, tau_m,
                                theta_s, theta_v, out, n);
}